// round 13
// baseline (speedup 1.0000x reference)
#include <cuda_runtime.h>
#include <stdint.h>

#define BB   4
#define NQ   2048
#define NP_  8192
#define DD   256
#define FF   40
#define KK   16
#define FULL 0xFFFFFFFFu

__device__ unsigned long long g_qcode[BB * NQ];
__device__ unsigned long long g_pcode[BB * NP_];

// ---- packed f32x2 helpers (Blackwell FFMA2) --------------------------------
__device__ __forceinline__ unsigned long long pk2(float a, float b) {
    unsigned long long r;
    asm("mov.b64 %0, {%1, %2};" : "=l"(r) : "f"(a), "f"(b));
    return r;
}
__device__ __forceinline__ unsigned long long ffma2(
    unsigned long long a, unsigned long long b, unsigned long long c) {
    unsigned long long d;
    asm("fma.rn.f32x2 %0, %1, %2, %3;" : "=l"(d) : "l"(a), "l"(b), "l"(c));
    return d;
}
__device__ __forceinline__ float hsum2(unsigned long long v) {
    float lo, hi;
    asm("mov.b64 {%0, %1}, %2;" : "=f"(lo), "=f"(hi) : "l"(v));
    return lo + hi;
}

// ---------------------------------------------------------------------------
// Hash kernel: one warp per 4 rows; proj smem traffic amortized 4x; packed
// FFMA2 dot products; 8-feature multi-reduction + ballot sign extraction
// (ordering identical to the verified round-8 kernel).
// ---------------------------------------------------------------------------
__global__ __launch_bounds__(256) void hash_kernel(
    const float* __restrict__ qpts,
    const float* __restrict__ ppts,
    const float* __restrict__ proj,
    unsigned long long* __restrict__ qcodes,
    unsigned long long* __restrict__ pcodes)
{
    __shared__ float sproj[FF * DD];  // 40 KB
    {
        const float4* p4 = reinterpret_cast<const float4*>(proj);
        float4* s4 = reinterpret_cast<float4*>(sproj);
        for (int i = threadIdx.x; i < (FF * DD) / 4; i += blockDim.x)
            s4[i] = p4[i];
    }
    __syncthreads();

    const int warp = threadIdx.x >> 5;
    const int lane = threadIdx.x & 31;
    const int row0 = (blockIdx.x * 8 + warp) * 4;   // 1280*8*4 = 40960 exact

    const int NQT = BB * NQ;
    const float* src;
    unsigned long long* dst;
    int r0;
    if (row0 < NQT) { src = qpts; dst = qcodes; r0 = row0; }
    else            { src = ppts; dst = pcodes; r0 = row0 - NQT; }

    unsigned long long vp[4][4];
#pragma unroll
    for (int r = 0; r < 4; ++r) {
        const float4* r4 = reinterpret_cast<const float4*>(src + (size_t)(r0 + r) * DD);
        float4 a = __ldg(r4 + lane);
        float4 b = __ldg(r4 + lane + 32);
        vp[r][0] = pk2(a.x, a.y);
        vp[r][1] = pk2(a.z, a.w);
        vp[r][2] = pk2(b.x, b.y);
        vp[r][3] = pk2(b.z, b.w);
    }

    const bool hi16 = (lane & 16) != 0;
    const bool hi8  = (lane & 8)  != 0;
    const bool hi4  = (lane & 4)  != 0;

    unsigned long long code[4] = {0ull, 0ull, 0ull, 0ull};

#pragma unroll
    for (int g = 0; g < 5; ++g) {
        const int brev[8] = {0, 4, 2, 6, 1, 5, 3, 7};
        float t[4][8];
#pragma unroll
        for (int s = 0; s < 8; ++s) {
            const int f = g * 8 + brev[s];
            const float4* sp = reinterpret_cast<const float4*>(sproj + f * DD);
            float4 p0 = sp[lane];
            float4 p1 = sp[lane + 32];
            unsigned long long pp0 = pk2(p0.x, p0.y);
            unsigned long long pp1 = pk2(p0.z, p0.w);
            unsigned long long pp2 = pk2(p1.x, p1.y);
            unsigned long long pp3 = pk2(p1.z, p1.w);
#pragma unroll
            for (int r = 0; r < 4; ++r) {
                unsigned long long acc = ffma2(vp[r][0], pp0, 0ull);
                acc = ffma2(vp[r][1], pp1, acc);
                acc = ffma2(vp[r][2], pp2, acc);
                acc = ffma2(vp[r][3], pp3, acc);
                t[r][s] = hsum2(acc);
            }
        }
#pragma unroll
        for (int r = 0; r < 4; ++r) {
            float rr[4];
#pragma unroll
            for (int p = 0; p < 4; ++p) {
                float c = hi16 ? t[r][2 * p + 1] : t[r][2 * p];
                float d = hi16 ? t[r][2 * p]     : t[r][2 * p + 1];
                rr[p] = c + __shfl_xor_sync(FULL, d, 16);
            }
            float ss[2];
#pragma unroll
            for (int p = 0; p < 2; ++p) {
                float c = hi8 ? rr[2 * p + 1] : rr[2 * p];
                float d = hi8 ? rr[2 * p]     : rr[2 * p + 1];
                ss[p] = c + __shfl_xor_sync(FULL, d, 8);
            }
            float c = hi4 ? ss[1] : ss[0];
            float d = hi4 ? ss[0] : ss[1];
            float u = c + __shfl_xor_sync(FULL, d, 4);
            u += __shfl_xor_sync(FULL, u, 2);
            u += __shfl_xor_sync(FULL, u, 1);

            unsigned bal = __ballot_sync(FULL, u > 0.0f);
            unsigned x = bal & 0x11111111u;
            x = (x | (x >> 3))  & 0x03030303u;
            x = (x | (x >> 6))  & 0x000F000Fu;
            x = (x | (x >> 12)) & 0xFFu;
            code[r] |= (unsigned long long)x << (g * 8);
        }
    }
    if (lane == 0) {
        dst[r0 + 0] = code[0];
        dst[r0 + 1] = code[1];
        dst[r0 + 2] = code[2];
        dst[r0 + 3] = code[3];
    }
}

// ---------------------------------------------------------------------------
// knn kernel: one warp per query, warp-distributed exact top-16.
// 8 candidates per lane per ballot round (4x LDG.128, 32 rounds).
// key = dist*8192 + idx (unique; matches lax.top_k tie ordering exactly).
// ---------------------------------------------------------------------------
__global__ __launch_bounds__(256) void knn_kernel(float* __restrict__ out)
{
    const int gwarp = (blockIdx.x * blockDim.x + threadIdx.x) >> 5;
    const int lane  = threadIdx.x & 31;
    const int b     = gwarp >> 11;

    const unsigned long long qc = g_qcode[gwarp];
    const ulonglong2* __restrict__ pc2 =
        reinterpret_cast<const ulonglong2*>(g_pcode + (size_t)b * NP_);

    unsigned lst = FULL;
    unsigned thr = FULL;

    auto try_insert = [&](unsigned key) {
        unsigned mask = __ballot_sync(FULL, key < thr);
        while (mask) {
            const int src = __ffs(mask) - 1;
            mask &= mask - 1;
            const unsigned kb  = __shfl_sync(FULL, key, src);
            const unsigned blt = __ballot_sync(FULL, lst < kb);
            const int pos = __popc(blt);
            if (pos < KK) {
                const unsigned up = __shfl_up_sync(FULL, lst, 1);
                if (lane < KK) {
                    if (lane > pos)       lst = up;
                    else if (lane == pos) lst = kb;
                }
                thr = __shfl_sync(FULL, lst, KK - 1);
                mask &= __ballot_sync(FULL, key < thr);
            }
        }
    };

    const unsigned lidx = lane * 2;
#pragma unroll 2
    for (int i = 0; i < NP_ / 256; ++i) {   // 32 rounds, 8 candidates/lane
        const int base = i * 128;           // ulonglong2 units
        const ulonglong2 c0 = __ldg(pc2 + base + lane);
        const ulonglong2 c1 = __ldg(pc2 + base + 32 + lane);
        const ulonglong2 c2 = __ldg(pc2 + base + 64 + lane);
        const ulonglong2 c3 = __ldg(pc2 + base + 96 + lane);
        const unsigned i0 = (unsigned)(base * 2) + lidx;
        const unsigned k0 = (unsigned)__popcll(qc ^ c0.x) * 8192u + i0;
        const unsigned k1 = (unsigned)__popcll(qc ^ c0.y) * 8192u + (i0 + 1);
        const unsigned k2 = (unsigned)__popcll(qc ^ c1.x) * 8192u + (i0 + 64);
        const unsigned k3 = (unsigned)__popcll(qc ^ c1.y) * 8192u + (i0 + 65);
        const unsigned k4 = (unsigned)__popcll(qc ^ c2.x) * 8192u + (i0 + 128);
        const unsigned k5 = (unsigned)__popcll(qc ^ c2.y) * 8192u + (i0 + 129);
        const unsigned k6 = (unsigned)__popcll(qc ^ c3.x) * 8192u + (i0 + 192);
        const unsigned k7 = (unsigned)__popcll(qc ^ c3.y) * 8192u + (i0 + 193);
        const unsigned m01 = min(k0, k1), m23 = min(k2, k3);
        const unsigned m45 = min(k4, k5), m67 = min(k6, k7);
        const unsigned m = min(min(m01, m23), min(m45, m67));
        if (__any_sync(FULL, m < thr)) {
            try_insert(k0); try_insert(k1); try_insert(k2); try_insert(k3);
            try_insert(k4); try_insert(k5); try_insert(k6); try_insert(k7);
        }
    }

    if (lane < KK) {
        const unsigned idx  = lst & 0x1FFFu;
        const float    dist = (float)(lst >> 13);
        const size_t basep = (size_t)gwarp * KK + lane;
        out[basep] = (float)idx;
        out[(size_t)BB * NQ * KK + basep] = dist;
    }
}

// ---------------------------------------------------------------------------
extern "C" void kernel_launch(void* const* d_in, const int* in_sizes, int n_in,
                              void* d_out, int out_size)
{
    const float* qpts = (const float*)d_in[0];
    const float* pts  = (const float*)d_in[1];
    const float* proj = (const float*)d_in[2];
    float* out = (float*)d_out;

    unsigned long long* qcode_ptr;
    unsigned long long* pcode_ptr;
    cudaGetSymbolAddress((void**)&qcode_ptr, g_qcode);
    cudaGetSymbolAddress((void**)&pcode_ptr, g_pcode);

    hash_kernel<<<1280, 256>>>(qpts, pts, proj, qcode_ptr, pcode_ptr);
    knn_kernel<<<1024, 256>>>(out);
}

// round 14
// speedup vs baseline: 1.1209x; 1.1209x over previous
#include <cuda_runtime.h>
#include <stdint.h>

#define BB   4
#define NQ   2048
#define NP_  8192
#define DD   256
#define FF   40
#define KK   16
#define FULL 0xFFFFFFFFu

__device__ unsigned long long g_qcode[BB * NQ];
__device__ unsigned long long g_pcode[BB * NP_];

// ---- packed f32x2 helpers (Blackwell FFMA2) --------------------------------
__device__ __forceinline__ unsigned long long pk2(float a, float b) {
    unsigned long long r;
    asm("mov.b64 %0, {%1, %2};" : "=l"(r) : "f"(a), "f"(b));
    return r;
}
__device__ __forceinline__ unsigned long long ffma2(
    unsigned long long a, unsigned long long b, unsigned long long c) {
    unsigned long long d;
    asm("fma.rn.f32x2 %0, %1, %2, %3;" : "=l"(d) : "l"(a), "l"(b), "l"(c));
    return d;
}
__device__ __forceinline__ float hsum2(unsigned long long v) {
    float lo, hi;
    asm("mov.b64 {%0, %1}, %2;" : "=f"(lo), "=f"(hi) : "l"(v));
    return lo + hi;
}

// ---------------------------------------------------------------------------
// Hash kernel (unchanged from verified round-8/13 kernel): one warp per 4
// rows; proj smem traffic amortized 4x; packed FFMA2 dot products; 8-feature
// multi-reduction + ballot sign extraction.
// ---------------------------------------------------------------------------
__global__ __launch_bounds__(256) void hash_kernel(
    const float* __restrict__ qpts,
    const float* __restrict__ ppts,
    const float* __restrict__ proj,
    unsigned long long* __restrict__ qcodes,
    unsigned long long* __restrict__ pcodes)
{
    __shared__ float sproj[FF * DD];  // 40 KB
    {
        const float4* p4 = reinterpret_cast<const float4*>(proj);
        float4* s4 = reinterpret_cast<float4*>(sproj);
        for (int i = threadIdx.x; i < (FF * DD) / 4; i += blockDim.x)
            s4[i] = p4[i];
    }
    __syncthreads();

    const int warp = threadIdx.x >> 5;
    const int lane = threadIdx.x & 31;
    const int row0 = (blockIdx.x * 8 + warp) * 4;   // 1280*8*4 = 40960 exact

    const int NQT = BB * NQ;
    const float* src;
    unsigned long long* dst;
    int r0;
    if (row0 < NQT) { src = qpts; dst = qcodes; r0 = row0; }
    else            { src = ppts; dst = pcodes; r0 = row0 - NQT; }

    unsigned long long vp[4][4];
#pragma unroll
    for (int r = 0; r < 4; ++r) {
        const float4* r4 = reinterpret_cast<const float4*>(src + (size_t)(r0 + r) * DD);
        float4 a = __ldg(r4 + lane);
        float4 b = __ldg(r4 + lane + 32);
        vp[r][0] = pk2(a.x, a.y);
        vp[r][1] = pk2(a.z, a.w);
        vp[r][2] = pk2(b.x, b.y);
        vp[r][3] = pk2(b.z, b.w);
    }

    const bool hi16 = (lane & 16) != 0;
    const bool hi8  = (lane & 8)  != 0;
    const bool hi4  = (lane & 4)  != 0;

    unsigned long long code[4] = {0ull, 0ull, 0ull, 0ull};

#pragma unroll
    for (int g = 0; g < 5; ++g) {
        const int brev[8] = {0, 4, 2, 6, 1, 5, 3, 7};
        float t[4][8];
#pragma unroll
        for (int s = 0; s < 8; ++s) {
            const int f = g * 8 + brev[s];
            const float4* sp = reinterpret_cast<const float4*>(sproj + f * DD);
            float4 p0 = sp[lane];
            float4 p1 = sp[lane + 32];
            unsigned long long pp0 = pk2(p0.x, p0.y);
            unsigned long long pp1 = pk2(p0.z, p0.w);
            unsigned long long pp2 = pk2(p1.x, p1.y);
            unsigned long long pp3 = pk2(p1.z, p1.w);
#pragma unroll
            for (int r = 0; r < 4; ++r) {
                unsigned long long acc = ffma2(vp[r][0], pp0, 0ull);
                acc = ffma2(vp[r][1], pp1, acc);
                acc = ffma2(vp[r][2], pp2, acc);
                acc = ffma2(vp[r][3], pp3, acc);
                t[r][s] = hsum2(acc);
            }
        }
#pragma unroll
        for (int r = 0; r < 4; ++r) {
            float rr[4];
#pragma unroll
            for (int p = 0; p < 4; ++p) {
                float c = hi16 ? t[r][2 * p + 1] : t[r][2 * p];
                float d = hi16 ? t[r][2 * p]     : t[r][2 * p + 1];
                rr[p] = c + __shfl_xor_sync(FULL, d, 16);
            }
            float ss[2];
#pragma unroll
            for (int p = 0; p < 2; ++p) {
                float c = hi8 ? rr[2 * p + 1] : rr[2 * p];
                float d = hi8 ? rr[2 * p]     : rr[2 * p + 1];
                ss[p] = c + __shfl_xor_sync(FULL, d, 8);
            }
            float c = hi4 ? ss[1] : ss[0];
            float d = hi4 ? ss[0] : ss[1];
            float u = c + __shfl_xor_sync(FULL, d, 4);
            u += __shfl_xor_sync(FULL, u, 2);
            u += __shfl_xor_sync(FULL, u, 1);

            unsigned bal = __ballot_sync(FULL, u > 0.0f);
            unsigned x = bal & 0x11111111u;
            x = (x | (x >> 3))  & 0x03030303u;
            x = (x | (x >> 6))  & 0x000F000Fu;
            x = (x | (x >> 12)) & 0xFFu;
            code[r] |= (unsigned long long)x << (g * 8);
        }
    }
    if (lane == 0) {
        dst[r0 + 0] = code[0];
        dst[r0 + 1] = code[1];
        dst[r0 + 2] = code[2];
        dst[r0 + 3] = code[3];
    }
}

// ---------------------------------------------------------------------------
// knn kernel v3: one warp per query.
// Phase 1 (branchless scan): each lane reduces its 256 candidates into 8
//   group-minimum keys (groups of 32 candidates = 4 rounds x 8 cands); after
//   each group, one warp-collective try_insert of the 32 group minima.
//   After the scan, lst = exact top-16 of all 256 group minima and
//   thr = 16th-smallest group minimum.
// Phase 2 (exact rescan): any true top-16 key k in group G satisfies
//   gmin_G <= k; if gmin_G > thr then >=16 group minima (actual keys) are
//   < gmin_G <= k, so k is not top-16. Hence rescanning exactly the groups
//   with gmin <= thr (<=16 of them, keys unique) recovers the exact answer.
//   Dedup: a group's min with gval <= current thr is provably still resident
//   in lst (unique keys, thr = lst[15]), so the rescan masks it to FULL.
// key = dist*8192 + idx  -> identical ordering to jax.lax.top_k.
// ---------------------------------------------------------------------------
__global__ __launch_bounds__(256) void knn_kernel(float* __restrict__ out)
{
    const int gwarp = (blockIdx.x * blockDim.x + threadIdx.x) >> 5;
    const int lane  = threadIdx.x & 31;
    const int b     = gwarp >> 11;

    const unsigned long long qc = g_qcode[gwarp];
    const unsigned long long* __restrict__ pc = g_pcode + (size_t)b * NP_;
    const ulonglong2* __restrict__ pc2 = reinterpret_cast<const ulonglong2*>(pc);

    unsigned lst = FULL;   // lanes >= 16 keep FULL forever
    unsigned thr = FULL;

    auto try_insert = [&](unsigned key) {
        unsigned mask = __ballot_sync(FULL, key < thr);
        while (mask) {
            const int src = __ffs(mask) - 1;
            mask &= mask - 1;
            const unsigned kb  = __shfl_sync(FULL, key, src);
            const unsigned blt = __ballot_sync(FULL, lst < kb);
            const int pos = __popc(blt);
            if (pos < KK) {
                const unsigned up = __shfl_up_sync(FULL, lst, 1);
                if (lane < KK) {
                    if (lane > pos)       lst = up;
                    else if (lane == pos) lst = kb;
                }
                thr = __shfl_sync(FULL, lst, KK - 1);
                mask &= __ballot_sync(FULL, key < thr);
            }
        }
    };

    // ---------------- Phase 1: branchless group-min scan ----------------
    unsigned gm[8];
    const unsigned lidx = lane * 2;
#pragma unroll
    for (int g = 0; g < 8; ++g) {
        unsigned gmin = FULL;
        for (int r = 0; r < 4; ++r) {          // dynamic: small code footprint
            const int base = (g * 4 + r) * 128;  // ulonglong2 units
            const ulonglong2 c0 = __ldg(pc2 + base + lane);
            const ulonglong2 c1 = __ldg(pc2 + base + 32 + lane);
            const ulonglong2 c2 = __ldg(pc2 + base + 64 + lane);
            const ulonglong2 c3 = __ldg(pc2 + base + 96 + lane);
            const unsigned i0 = (unsigned)(base * 2) + lidx;
            const unsigned k0 = (unsigned)__popcll(qc ^ c0.x) * 8192u + i0;
            const unsigned k1 = (unsigned)__popcll(qc ^ c0.y) * 8192u + (i0 + 1);
            const unsigned k2 = (unsigned)__popcll(qc ^ c1.x) * 8192u + (i0 + 64);
            const unsigned k3 = (unsigned)__popcll(qc ^ c1.y) * 8192u + (i0 + 65);
            const unsigned k4 = (unsigned)__popcll(qc ^ c2.x) * 8192u + (i0 + 128);
            const unsigned k5 = (unsigned)__popcll(qc ^ c2.y) * 8192u + (i0 + 129);
            const unsigned k6 = (unsigned)__popcll(qc ^ c3.x) * 8192u + (i0 + 192);
            const unsigned k7 = (unsigned)__popcll(qc ^ c3.y) * 8192u + (i0 + 193);
            const unsigned m01 = min(k0, k1), m23 = min(k2, k3);
            const unsigned m45 = min(k4, k5), m67 = min(k6, k7);
            gmin = min(gmin, min(min(m01, m23), min(m45, m67)));
        }
        gm[g] = gmin;
        try_insert(gmin);
    }

    // ---------------- Phase 2: exact rescan of candidate groups ----------------
#pragma unroll
    for (int g = 0; g < 8; ++g) {
        unsigned mask = __ballot_sync(FULL, gm[g] <= thr);
        while (mask) {
            const int src = __ffs(mask) - 1;
            mask &= mask - 1;
            const unsigned gval = __shfl_sync(FULL, gm[g], src);
            // lane m rescans candidate m of group (src, g):
            //   round i = 4g + m/8, slot offset = (m&1) + ((m>>1)&3)*64
            const int i   = g * 4 + (lane >> 3);
            const int idx = i * 256 + src * 2 + ((lane >> 1) & 3) * 64 + (lane & 1);
            const unsigned long long c = __ldg(pc + idx);
            unsigned key = (unsigned)__popcll(qc ^ c) * 8192u + (unsigned)idx;
            if (key == gval) key = FULL;   // dedup: group min already in lst
            try_insert(key);
            mask &= __ballot_sync(FULL, gm[g] <= thr);  // prune with shrunken thr
        }
    }

    if (lane < KK) {
        const unsigned idx  = lst & 0x1FFFu;
        const float    dist = (float)(lst >> 13);
        const size_t basep = (size_t)gwarp * KK + lane;
        out[basep] = (float)idx;
        out[(size_t)BB * NQ * KK + basep] = dist;
    }
}

// ---------------------------------------------------------------------------
extern "C" void kernel_launch(void* const* d_in, const int* in_sizes, int n_in,
                              void* d_out, int out_size)
{
    const float* qpts = (const float*)d_in[0];
    const float* pts  = (const float*)d_in[1];
    const float* proj = (const float*)d_in[2];
    float* out = (float*)d_out;

    unsigned long long* qcode_ptr;
    unsigned long long* pcode_ptr;
    cudaGetSymbolAddress((void**)&qcode_ptr, g_qcode);
    cudaGetSymbolAddress((void**)&pcode_ptr, g_pcode);

    hash_kernel<<<1280, 256>>>(qpts, pts, proj, qcode_ptr, pcode_ptr);
    knn_kernel<<<1024, 256>>>(out);
}